// round 14
// baseline (speedup 1.0000x reference)
#include <cuda_runtime.h>
#include <cuda_bf16.h>
#include <math.h>
#include <stdint.h>

#define BB 4
#define CC 256
#define CQ 32
#define NN 3136
#define MP 320                // packed projection rows: 32 q + 32 k + 256 v

// flash tiling
#define BM 64                 // query rows per CTA (was 32)
#define BJ 64                 // keys per stage
#define NST (NN / BJ)         // 49 stages
#define KP 40                 // K smem pitch (bf16)
#define VP 72                 // V smem pitch (bf16)
#define PP 72                 // P smem pitch (bf16)
#define KSTG (BJ * KP)        // 2560 elems
#define VSTG (CC * VP)        // 18432 elems
#define OBP 257               // O transpose buffer pitch (floats)
#define PS_OFF (2 * KSTG * 2 + 2 * VSTG * 2)   // 83968: P tile [64][PP]
#define LS_OFF (PS_OFF + 64 * PP * 2)          // 93184: l partials float[4][64]
#define SMEM_BYTES (LS_OFF + 256 * 4)          // 94208

// ---------------- scratch ----------------
__device__ __nv_bfloat16 g_qh[(size_t)BB * NN * CQ];   // q [B][N][32] (pre-scaled by 1/norm)
__device__ __nv_bfloat16 g_kh[(size_t)BB * NN * CQ];   // k [B][N][32]
__device__ __nv_bfloat16 g_vh[(size_t)BB * CC * NN];   // v [B][C][N]
__device__ __nv_bfloat16 g_xt[(size_t)BB * NN * CC];   // x^T bf16 [B][N][C]
__device__ __nv_bfloat16 g_wh[(size_t)MP * CC];        // [Wq;Wk;Wv] bf16 [320][256]
__device__ float g_scalars[4];                         // [0] = 1/norm_value

// ---------------- helpers ----------------
__device__ __forceinline__ float warpRedMax(float v) {
#pragma unroll
    for (int o = 16; o > 0; o >>= 1) v = fmaxf(v, __shfl_xor_sync(0xffffffffu, v, o));
    return v;
}
__device__ __forceinline__ float warpRedSum(float v) {
#pragma unroll
    for (int o = 16; o > 0; o >>= 1) v += __shfl_xor_sync(0xffffffffu, v, o);
    return v;
}

__device__ __forceinline__ void mma_bf16(float* d, uint32_t a0, uint32_t a1,
                                         uint32_t a2, uint32_t a3,
                                         uint32_t b0, uint32_t b1) {
    asm volatile(
        "mma.sync.aligned.m16n8k16.row.col.f32.bf16.bf16.f32 "
        "{%0,%1,%2,%3}, {%4,%5,%6,%7}, {%8,%9}, {%0,%1,%2,%3};\n"
        : "+f"(d[0]), "+f"(d[1]), "+f"(d[2]), "+f"(d[3])
        : "r"(a0), "r"(a1), "r"(a2), "r"(a3), "r"(b0), "r"(b1));
}

__device__ __forceinline__ void ldsm4(uint32_t& r0, uint32_t& r1, uint32_t& r2,
                                      uint32_t& r3, uint32_t a) {
    asm volatile(
        "ldmatrix.sync.aligned.m8n8.x4.shared.b16 {%0,%1,%2,%3}, [%4];\n"
        : "=r"(r0), "=r"(r1), "=r"(r2), "=r"(r3)
        : "r"(a));
}

__device__ __forceinline__ void cp16(uint32_t dst_smem, const void* src) {
    asm volatile("cp.async.cg.shared.global [%0], [%1], 16;\n" ::"r"(dst_smem),
                 "l"(src));
}
#define CP_COMMIT() asm volatile("cp.async.commit_group;\n" ::: "memory")
#define CP_WAIT1() asm volatile("cp.async.wait_group 1;\n" ::: "memory")
#define CP_WAIT0() asm volatile("cp.async.wait_group 0;\n" ::: "memory")

__device__ __forceinline__ uint32_t pack_bf16(float a, float b) {
    __nv_bfloat162 h = __floats2bfloat162_rn(a, b);
    return *(uint32_t*)&h;
}

// ---------------- norm_value ----------------
__global__ void norm_kernel(const float* __restrict__ Wq,
                            const float* __restrict__ Wk,
                            const float* __restrict__ Wv) {
    __shared__ float ssum[8];
    __shared__ float smax[8];
    int tid = threadIdx.x, lane = tid & 31, wid = tid >> 5;

    float s = 0.f;
    for (int i = tid; i < CQ * CC; i += 256) { float w = Wq[i]; s = fmaf(w, w, s); }

    float vk = 0.f;
#pragma unroll
    for (int o = 0; o < CQ; o++) { float w = Wk[o * CC + tid]; vk = fmaf(w, w, vk); }
    float vv = 0.f;
    for (int o = 0; o < CC; o++) { float w = Wv[o * CC + tid]; vv = fmaf(w, w, vv); }
    float m = fmaxf(vk, vv);

    s = warpRedSum(s);
    m = warpRedMax(m);
    if (lane == 0) { ssum[wid] = s; smax[wid] = m; }
    __syncthreads();
    if (tid == 0) {
        float u2 = 0.f, mm = -1e30f;
#pragma unroll
        for (int i = 0; i < 8; i++) { u2 += ssum[i]; mm = fmaxf(mm, smax[i]); }
        g_scalars[0] = 1.0f / (sqrtf(u2) * sqrtf(mm));
    }
}

// ---------------- pack weights -> bf16 [320][256] ----------------
__global__ void prep_w(const float* __restrict__ Wq, const float* __restrict__ Wk,
                       const float* __restrict__ Wv) {
    int row = blockIdx.x;
    int c = threadIdx.x;
    float w;
    if (row < 32) w = Wq[row * CC + c];
    else if (row < 64) w = Wk[(row - 32) * CC + c];
    else w = Wv[(row - 64) * CC + c];
    g_wh[row * CC + c] = __float2bfloat16(w);
}

// ---------------- transpose + convert x -> bf16 [B][N][C] ----------------
__global__ __launch_bounds__(256) void xpose(const float* __restrict__ x) {
    __shared__ float t[32][33];
    const int b = blockIdx.z;
    const int n0 = blockIdx.x * 32;
    const int c0 = blockIdx.y * 32;
    const int tx = threadIdx.x & 31;
    const int ty = threadIdx.x >> 5;

    const float* xb = x + (size_t)b * CC * NN;
#pragma unroll
    for (int p = 0; p < 4; p++) {
        int cl = ty + p * 8;
        t[cl][tx] = xb[(size_t)(c0 + cl) * NN + n0 + tx];
    }
    __syncthreads();
    __nv_bfloat16* xt = g_xt + (size_t)b * NN * CC;
#pragma unroll
    for (int p = 0; p < 4; p++) {
        int r = ty + p * 8;
        xt[(size_t)(n0 + r) * CC + c0 + tx] = __float2bfloat16(t[tx][r]);
    }
}

// ---------------- fused projection GEMM (tensor cores), superbatched ----------------
__global__ __launch_bounds__(256) void proj_mma(const float* __restrict__ bq,
                                                const float* __restrict__ bk,
                                                const float* __restrict__ bv) {
    constexpr int KT = 64;
    constexpr int PITCH = KT + 8;
    __shared__ __nv_bfloat16 As[128 * PITCH];
    __shared__ __nv_bfloat16 Bs[128 * PITCH];

    const int tid = threadIdx.x;
    const int lane = tid & 31;
    const int wid = tid >> 5;
    const int wm = (wid >> 2) * 64;
    const int wn = (wid & 3) * 32;
    const int bz2 = blockIdx.z * 2;
    const int m0 = blockIdx.y * 128;
    const int n0 = blockIdx.x * 128;  // flat n in [0, 6272)

    float acc[4][4][4];
#pragma unroll
    for (int a = 0; a < 4; a++)
#pragma unroll
        for (int b2 = 0; b2 < 4; b2++)
#pragma unroll
            for (int c = 0; c < 4; c++) acc[a][b2][c] = 0.f;

    const int lk = (tid & 7) * 8;
    const int lrow = tid >> 3;

    for (int k0 = 0; k0 < CC; k0 += KT) {
#pragma unroll
        for (int p = 0; p < 4; p++) {
            int r = lrow + p * 32;
            int grow = m0 + r;
            uint4 v = make_uint4(0u, 0u, 0u, 0u);
            if (grow < MP) v = *(const uint4*)(g_wh + (size_t)grow * CC + k0 + lk);
            *(uint4*)&As[r * PITCH + lk] = v;
        }
#pragma unroll
        for (int p = 0; p < 4; p++) {
            int r = lrow + p * 32;
            int fr = n0 + r;
            int bl = fr >= NN;
            int nr = fr - (bl ? NN : 0);
            const __nv_bfloat16* Bp =
                g_xt + ((size_t)(bz2 + bl) * NN + nr) * CC;
            uint4 v = *(const uint4*)(Bp + k0 + lk);
            *(uint4*)&Bs[r * PITCH + lk] = v;
        }
        __syncthreads();

#pragma unroll
        for (int kk = 0; kk < KT / 16; kk++) {
            const int kb = kk * 16;
            uint32_t af[4][4], bf[4][2];
#pragma unroll
            for (int mi = 0; mi < 4; mi++) {
                const __nv_bfloat16* p0 =
                    &As[(wm + mi * 16 + (lane >> 2)) * PITCH + kb + (lane & 3) * 2];
                af[mi][0] = *(const uint32_t*)p0;
                af[mi][1] = *(const uint32_t*)(p0 + 8 * PITCH);
                af[mi][2] = *(const uint32_t*)(p0 + 8);
                af[mi][3] = *(const uint32_t*)(p0 + 8 * PITCH + 8);
            }
#pragma unroll
            for (int ni = 0; ni < 4; ni++) {
                const __nv_bfloat16* p0 =
                    &Bs[(wn + ni * 8 + (lane >> 2)) * PITCH + kb + (lane & 3) * 2];
                bf[ni][0] = *(const uint32_t*)p0;
                bf[ni][1] = *(const uint32_t*)(p0 + 8);
            }
#pragma unroll
            for (int mi = 0; mi < 4; mi++)
#pragma unroll
                for (int ni = 0; ni < 4; ni++)
                    mma_bf16(acc[mi][ni], af[mi][0], af[mi][1], af[mi][2], af[mi][3],
                             bf[ni][0], bf[ni][1]);
        }
        __syncthreads();
    }

    const float qs = g_scalars[0];
    auto store_row = [&](int row, int fcol, float v0, float v1) {
        if (row >= MP) return;
        int bl = fcol >= NN;
        int col = fcol - (bl ? NN : 0);
        int bb = bz2 + bl;
        float bias = (row < 32) ? bq[row] : (row < 64) ? bk[row - 32] : bv[row - 64];
        v0 += bias; v1 += bias;
        if (row < 32) {
            __nv_bfloat16* q = g_qh + (size_t)bb * NN * CQ;
            q[(size_t)col * CQ + row] = __float2bfloat16(v0 * qs);
            q[(size_t)(col + 1) * CQ + row] = __float2bfloat16(v1 * qs);
        } else if (row < 64) {
            __nv_bfloat16* k = g_kh + (size_t)bb * NN * CQ;
            k[(size_t)col * CQ + row - 32] = __float2bfloat16(v0);
            k[(size_t)(col + 1) * CQ + row - 32] = __float2bfloat16(v1);
        } else {
            __nv_bfloat16* v = g_vh + (size_t)bb * CC * NN;
            *(__nv_bfloat162*)(v + (size_t)(row - 64) * NN + col) =
                __floats2bfloat162_rn(v0, v1);
        }
    };

#pragma unroll
    for (int mi = 0; mi < 4; mi++)
#pragma unroll
        for (int ni = 0; ni < 4; ni++) {
            int row = m0 + wm + mi * 16 + (lane >> 2);
            int fcol = n0 + wn + ni * 8 + (lane & 3) * 2;
            store_row(row, fcol, acc[mi][ni][0], acc[mi][ni][1]);
            store_row(row + 8, fcol, acc[mi][ni][2], acc[mi][ni][3]);
        }
}

// ---------------- fused flash attention, BM=64, 512 threads ----------------
// 16 warps. S phase: 4m x 4j (each 16 rows x 16 keys). PV phase: 4m x 4c
// (each 16 rows x 64 channels). R12 two-barrier stage skeleton (proven).
// Halves V L2 traffic vs BM=32: 196 CTAs each stream V once.
__global__ __launch_bounds__(512, 1) void flash_kernel(float* __restrict__ out,
                                                       const float* __restrict__ xr,
                                                       const float* __restrict__ gamma,
                                                       float inv_bound) {
    extern __shared__ char dsm[];
    __nv_bfloat16* Ks = (__nv_bfloat16*)dsm;                   // 2*KSTG
    __nv_bfloat16* Vs = (__nv_bfloat16*)(dsm + 2 * KSTG * 2);  // 2*VSTG
    __nv_bfloat16* Ps = (__nv_bfloat16*)(dsm + PS_OFF);        // [64][PP]
    float* l_s = (float*)(dsm + LS_OFF);                       // [4][64]
    float* Obuf = (float*)(dsm);                               // epilogue reuse (64*257 f32)

    const int tid = threadIdx.x;
    const int lane = tid & 31;
    const int wid = tid >> 5;
    const int mw = wid >> 2;     // 0..3 : row quarter (16 rows)
    const int jw = wid & 3;      // S: key slice; PV: channel slice
    const int b = blockIdx.y;
    const int n0 = blockIdx.x * BM;

    const __nv_bfloat16* qg = g_qh + ((size_t)b * NN + n0 + mw * 16) * CQ;
    const __nv_bfloat16* kg = g_kh + (size_t)b * NN * CQ;
    const __nv_bfloat16* vg = g_vh + (size_t)b * CC * NN;

    uint32_t aq[2][4];
    {
        int r = lane >> 2;
#pragma unroll
        for (int kc = 0; kc < 2; kc++) {
            int kk = kc * 16 + (lane & 3) * 2;
            aq[kc][0] = *(const uint32_t*)(qg + (size_t)r * CQ + kk);
            aq[kc][1] = *(const uint32_t*)(qg + (size_t)(r + 8) * CQ + kk);
            aq[kc][2] = *(const uint32_t*)(qg + (size_t)r * CQ + kk + 8);
            aq[kc][3] = *(const uint32_t*)(qg + (size_t)(r + 8) * CQ + kk + 8);
        }
    }

    float o[8][4];
#pragma unroll
    for (int i = 0; i < 8; i++) { o[i][0] = o[i][1] = o[i][2] = o[i][3] = 0.f; }
    float accA = 0.f, accB = 0.f;

    const int krow = tid >> 2, kch = tid & 3;   // K: 64 rows x 4 chunks (tid<256)
    const int vrow = tid >> 3, vch = tid & 7;   // V: vrow 0..63, 4 passes of 64 ch
    auto load_stage = [&](int s, int buf) {
        int j0 = s * BJ;
        if (tid < 256)
            cp16((uint32_t)__cvta_generic_to_shared(Ks + buf * KSTG + krow * KP + kch * 8),
                 kg + (size_t)(j0 + krow) * CQ + kch * 8);
#pragma unroll
        for (int p = 0; p < 4; p++) {
            int c = vrow + p * 64;
            cp16((uint32_t)__cvta_generic_to_shared(Vs + buf * VSTG + c * VP + vch * 8),
                 vg + (size_t)c * NN + j0 + vch * 8);
        }
    };

    // ldmatrix lane base addresses (shared space, bytes)
    const uint32_t ksb = (uint32_t)__cvta_generic_to_shared(Ks) +
                         ((jw * 16 + (lane & 7)) * KP + (lane >> 3) * 8) * 2;
    const uint32_t vsb = (uint32_t)__cvta_generic_to_shared(Vs) +
                         ((jw * 64 + (lane >> 4) * 8 + (lane & 7)) * VP +
                          ((lane >> 3) & 1) * 8) * 2;
    const uint32_t psb = (uint32_t)__cvta_generic_to_shared(Ps) +
                         ((mw * 16 + (lane & 15)) * PP + (lane >> 4) * 8) * 2;

    const int prow = mw * 16 + (lane >> 2);
    __nv_bfloat16* pst = Ps + prow * PP + jw * 16 + (lane & 3) * 2;

    load_stage(0, 0);
    CP_COMMIT();

    for (int s = 0; s < NST; s++) {
        if (s + 1 < NST) {
            load_stage(s + 1, (s + 1) & 1);
            CP_COMMIT();
            CP_WAIT1();
        } else {
            CP_WAIT0();
        }
        __syncthreads();   // K/V tile ready; previous PV done reading Ps

        const int buf = s & 1;
        const uint32_t kb = ksb + buf * (KSTG * 2);
        const uint32_t vb = vsb + buf * (VSTG * 2);

        // ---- S phase: this warp's 16 rows x 16 keys ----
#pragma unroll
        for (int nt = 0; nt < 2; nt++) {
            float sv[4];
            sv[0] = sv[1] = sv[2] = sv[3] = 0.f;
            uint32_t k0, k1, k2, k3;
            ldsm4(k0, k1, k2, k3, kb + nt * (8 * KP * 2));
            mma_bf16(sv, aq[0][0], aq[0][1], aq[0][2], aq[0][3], k0, k1);
            mma_bf16(sv, aq[1][0], aq[1][1], aq[1][2], aq[1][3], k2, k3);

            float p0 = __expf(fminf(sv[0], 60.f));
            float p1 = __expf(fminf(sv[1], 60.f));
            float p2 = __expf(fminf(sv[2], 60.f));
            float p3 = __expf(fminf(sv[3], 60.f));
            accA += p0 + p1;
            accB += p2 + p3;
            *(uint32_t*)(pst + nt * 8) = pack_bf16(p0, p1);
            *(uint32_t*)(pst + 8 * PP + nt * 8) = pack_bf16(p2, p3);
        }
        __syncthreads();   // full P tile visible

        // ---- PV phase: full 64 keys x this warp's 64 channels ----
        uint32_t ap[4][4];
#pragma unroll
        for (int kt = 0; kt < 4; kt++)
            ldsm4(ap[kt][0], ap[kt][1], ap[kt][2], ap[kt][3], psb + kt * 32);
#pragma unroll
        for (int kt = 0; kt < 4; kt++) {
#pragma unroll
            for (int ctp = 0; ctp < 4; ctp++) {
                uint32_t v0, v1, v2, v3;
                ldsm4(v0, v1, v2, v3, vb + ctp * (16 * VP * 2) + kt * 32);
                mma_bf16(o[2 * ctp], ap[kt][0], ap[kt][1], ap[kt][2], ap[kt][3],
                         v0, v1);
                mma_bf16(o[2 * ctp + 1], ap[kt][0], ap[kt][1], ap[kt][2], ap[kt][3],
                         v2, v3);
            }
        }
    }

    // ---- merge denominators across the 4 j-slices ----
    accA += __shfl_xor_sync(0xffffffffu, accA, 1);
    accA += __shfl_xor_sync(0xffffffffu, accA, 2);
    accB += __shfl_xor_sync(0xffffffffu, accB, 1);
    accB += __shfl_xor_sync(0xffffffffu, accB, 2);
    const int rA = mw * 16 + (lane >> 2);
    const int rB = rA + 8;
    if ((lane & 3) == 0) {
        l_s[jw * 64 + rA] = accA;
        l_s[jw * 64 + rB] = accB;
    }
    __syncthreads();
    const float invA =
        1.0f / (l_s[rA] + l_s[64 + rA] + l_s[128 + rA] + l_s[192 + rA]);
    const float invB =
        1.0f / (l_s[rB] + l_s[64 + rB] + l_s[128 + rB] + l_s[192 + rB]);
    __syncthreads();   // all l_s reads done; K/V smem reusable as Obuf

#pragma unroll
    for (int ct = 0; ct < 8; ct++) {
        int c = jw * 64 + ct * 8 + 2 * (lane & 3);
        float* pA = Obuf + rA * OBP + c;
        float* pB = Obuf + rB * OBP + c;
        pA[0] = o[ct][0] * invA; pA[1] = o[ct][1] * invA;
        pB[0] = o[ct][2] * invB; pB[1] = o[ct][3] * invB;
    }
    __syncthreads();

    const float gscale = gamma[0] * inv_bound;
    const float* xb = xr + (size_t)b * CC * NN;
    float* ob = out + (size_t)b * CC * NN;
    const int i = tid & 63;        // row within tile
    const int crow = tid >> 6;     // 0..7
    for (int cb = 0; cb < CC; cb += 8) {
        int c = cb + crow;
        float val = Obuf[i * OBP + c];
        size_t off = (size_t)c * NN + n0 + i;
        ob[off] = fmaf(gscale, val, xb[off]);
    }
}

// ---------------- launch ----------------
extern "C" void kernel_launch(void* const* d_in, const int* in_sizes, int n_in,
                              void* d_out, int out_size) {
    const float* x = (const float*)d_in[0];
    const float* Wq = (const float*)d_in[1];
    const float* bq = (const float*)d_in[2];
    const float* Wk = (const float*)d_in[3];
    const float* bk = (const float*)d_in[4];
    const float* Wv = (const float*)d_in[5];
    const float* bv = (const float*)d_in[6];
    const float* gamma = (const float*)d_in[7];
    float* out = (float*)d_out;

    cudaFuncSetAttribute(flash_kernel, cudaFuncAttributeMaxDynamicSharedMemorySize,
                         SMEM_BYTES);

    norm_kernel<<<1, 256>>>(Wq, Wk, Wv);
    prep_w<<<MP, CC>>>(Wq, Wk, Wv);
    xpose<<<dim3(NN / 32, CC / 32, BB), 256>>>(x);
    proj_mma<<<dim3(49, 3, 2), 256>>>(bq, bk, bv);

    double bound = exp(sqrt(3.0)) * sqrt((double)NN / (double)CC) + 2.0 * sqrt(6.0);
    float inv_bound = (float)(1.0 / bound);
    flash_kernel<<<dim3(NN / BM, BB), 512, SMEM_BYTES>>>(out, x, gamma, inv_bound);
}

// round 16
// speedup vs baseline: 1.1136x; 1.1136x over previous
#include <cuda_runtime.h>
#include <cuda_bf16.h>
#include <math.h>
#include <stdint.h>

#define BB 4
#define CC 256
#define CQ 32
#define NN 3136
#define MP 320                // packed projection rows: 32 q + 32 k + 256 v

// flash tiling
#define BM 32                 // query rows per CTA
#define BJ 64                 // keys per stage
#define NST (NN / BJ)         // 49 stages
#define KP 40                 // K smem pitch (bf16)
#define VP 72                 // V smem pitch (bf16)
#define PP 72                 // P smem pitch (bf16)
#define KSTG (BJ * KP)        // 2560 elems
#define VSTG (CC * VP)        // 18432 elems
#define OBP 257               // O transpose buffer pitch (floats)
#define PS_OFF (2 * KSTG * 2 + 2 * VSTG * 2)   // 83968: P tile [32][PP]
#define LS_OFF (PS_OFF + 32 * PP * 2)          // l partials float[4][32]
#define SMEM_BYTES (LS_OFF + 128 * 4)          // 89088

// ---------------- scratch ----------------
__device__ __nv_bfloat16 g_qh[(size_t)BB * NN * CQ];   // q [B][N][32] (pre-scaled by 1/norm)
__device__ __nv_bfloat16 g_kh[(size_t)BB * NN * CQ];   // k [B][N][32]
__device__ __nv_bfloat16 g_vh[(size_t)BB * CC * NN];   // v [B][C][N]
__device__ __nv_bfloat16 g_xt[(size_t)BB * NN * CC];   // x^T bf16 [B][N][C]
__device__ __nv_bfloat16 g_wh[(size_t)MP * CC];        // [Wq;Wk;Wv] bf16 [320][256]
__device__ float g_scalars[4];                         // [0] = 1/norm_value

// ---------------- helpers ----------------
__device__ __forceinline__ float warpRedMax(float v) {
#pragma unroll
    for (int o = 16; o > 0; o >>= 1) v = fmaxf(v, __shfl_xor_sync(0xffffffffu, v, o));
    return v;
}
__device__ __forceinline__ float warpRedSum(float v) {
#pragma unroll
    for (int o = 16; o > 0; o >>= 1) v += __shfl_xor_sync(0xffffffffu, v, o);
    return v;
}

__device__ __forceinline__ void mma_bf16(float* d, uint32_t a0, uint32_t a1,
                                         uint32_t a2, uint32_t a3,
                                         uint32_t b0, uint32_t b1) {
    asm volatile(
        "mma.sync.aligned.m16n8k16.row.col.f32.bf16.bf16.f32 "
        "{%0,%1,%2,%3}, {%4,%5,%6,%7}, {%8,%9}, {%0,%1,%2,%3};\n"
        : "+f"(d[0]), "+f"(d[1]), "+f"(d[2]), "+f"(d[3])
        : "r"(a0), "r"(a1), "r"(a2), "r"(a3), "r"(b0), "r"(b1));
}

__device__ __forceinline__ void ldsm4(uint32_t& r0, uint32_t& r1, uint32_t& r2,
                                      uint32_t& r3, uint32_t a) {
    asm volatile(
        "ldmatrix.sync.aligned.m8n8.x4.shared.b16 {%0,%1,%2,%3}, [%4];\n"
        : "=r"(r0), "=r"(r1), "=r"(r2), "=r"(r3)
        : "r"(a));
}

__device__ __forceinline__ void cp16(uint32_t dst_smem, const void* src) {
    asm volatile("cp.async.cg.shared.global [%0], [%1], 16;\n" ::"r"(dst_smem),
                 "l"(src));
}
#define CP_COMMIT() asm volatile("cp.async.commit_group;\n" ::: "memory")
#define CP_WAIT1() asm volatile("cp.async.wait_group 1;\n" ::: "memory")
#define CP_WAIT0() asm volatile("cp.async.wait_group 0;\n" ::: "memory")

__device__ __forceinline__ uint32_t pack_bf16(float a, float b) {
    __nv_bfloat162 h = __floats2bfloat162_rn(a, b);
    return *(uint32_t*)&h;
}

// ---------------- norm_value ----------------
__global__ void norm_kernel(const float* __restrict__ Wq,
                            const float* __restrict__ Wk,
                            const float* __restrict__ Wv) {
    __shared__ float ssum[8];
    __shared__ float smax[8];
    int tid = threadIdx.x, lane = tid & 31, wid = tid >> 5;

    float s = 0.f;
    for (int i = tid; i < CQ * CC; i += 256) { float w = Wq[i]; s = fmaf(w, w, s); }

    float vk = 0.f;
#pragma unroll
    for (int o = 0; o < CQ; o++) { float w = Wk[o * CC + tid]; vk = fmaf(w, w, vk); }
    float vv = 0.f;
    for (int o = 0; o < CC; o++) { float w = Wv[o * CC + tid]; vv = fmaf(w, w, vv); }
    float m = fmaxf(vk, vv);

    s = warpRedSum(s);
    m = warpRedMax(m);
    if (lane == 0) { ssum[wid] = s; smax[wid] = m; }
    __syncthreads();
    if (tid == 0) {
        float u2 = 0.f, mm = -1e30f;
#pragma unroll
        for (int i = 0; i < 8; i++) { u2 += ssum[i]; mm = fmaxf(mm, smax[i]); }
        g_scalars[0] = 1.0f / (sqrtf(u2) * sqrtf(mm));
    }
}

// ---------------- pack weights -> bf16 [320][256] ----------------
__global__ void prep_w(const float* __restrict__ Wq, const float* __restrict__ Wk,
                       const float* __restrict__ Wv) {
    int row = blockIdx.x;
    int c = threadIdx.x;
    float w;
    if (row < 32) w = Wq[row * CC + c];
    else if (row < 64) w = Wk[(row - 32) * CC + c];
    else w = Wv[(row - 64) * CC + c];
    g_wh[row * CC + c] = __float2bfloat16(w);
}

// ---------------- transpose + convert x -> bf16 [B][N][C] ----------------
__global__ __launch_bounds__(256) void xpose(const float* __restrict__ x) {
    __shared__ float t[32][33];
    const int b = blockIdx.z;
    const int n0 = blockIdx.x * 32;
    const int c0 = blockIdx.y * 32;
    const int tx = threadIdx.x & 31;
    const int ty = threadIdx.x >> 5;

    const float* xb = x + (size_t)b * CC * NN;
#pragma unroll
    for (int p = 0; p < 4; p++) {
        int cl = ty + p * 8;
        t[cl][tx] = xb[(size_t)(c0 + cl) * NN + n0 + tx];
    }
    __syncthreads();
    __nv_bfloat16* xt = g_xt + (size_t)b * NN * CC;
#pragma unroll
    for (int p = 0; p < 4; p++) {
        int r = ty + p * 8;
        xt[(size_t)(n0 + r) * CC + c0 + tx] = __float2bfloat16(t[tx][r]);
    }
}

// ---------------- fused projection GEMM (tensor cores), superbatched ----------------
__global__ __launch_bounds__(256) void proj_mma(const float* __restrict__ bq,
                                                const float* __restrict__ bk,
                                                const float* __restrict__ bv) {
    constexpr int KT = 64;
    constexpr int PITCH = KT + 8;
    __shared__ __nv_bfloat16 As[128 * PITCH];
    __shared__ __nv_bfloat16 Bs[128 * PITCH];

    const int tid = threadIdx.x;
    const int lane = tid & 31;
    const int wid = tid >> 5;
    const int wm = (wid >> 2) * 64;
    const int wn = (wid & 3) * 32;
    const int bz2 = blockIdx.z * 2;
    const int m0 = blockIdx.y * 128;
    const int n0 = blockIdx.x * 128;  // flat n in [0, 6272)

    float acc[4][4][4];
#pragma unroll
    for (int a = 0; a < 4; a++)
#pragma unroll
        for (int b2 = 0; b2 < 4; b2++)
#pragma unroll
            for (int c = 0; c < 4; c++) acc[a][b2][c] = 0.f;

    const int lk = (tid & 7) * 8;
    const int lrow = tid >> 3;

    for (int k0 = 0; k0 < CC; k0 += KT) {
#pragma unroll
        for (int p = 0; p < 4; p++) {
            int r = lrow + p * 32;
            int grow = m0 + r;
            uint4 v = make_uint4(0u, 0u, 0u, 0u);
            if (grow < MP) v = *(const uint4*)(g_wh + (size_t)grow * CC + k0 + lk);
            *(uint4*)&As[r * PITCH + lk] = v;
        }
#pragma unroll
        for (int p = 0; p < 4; p++) {
            int r = lrow + p * 32;
            int fr = n0 + r;
            int bl = fr >= NN;
            int nr = fr - (bl ? NN : 0);
            const __nv_bfloat16* Bp =
                g_xt + ((size_t)(bz2 + bl) * NN + nr) * CC;
            uint4 v = *(const uint4*)(Bp + k0 + lk);
            *(uint4*)&Bs[r * PITCH + lk] = v;
        }
        __syncthreads();

#pragma unroll
        for (int kk = 0; kk < KT / 16; kk++) {
            const int kb = kk * 16;
            uint32_t af[4][4], bf[4][2];
#pragma unroll
            for (int mi = 0; mi < 4; mi++) {
                const __nv_bfloat16* p0 =
                    &As[(wm + mi * 16 + (lane >> 2)) * PITCH + kb + (lane & 3) * 2];
                af[mi][0] = *(const uint32_t*)p0;
                af[mi][1] = *(const uint32_t*)(p0 + 8 * PITCH);
                af[mi][2] = *(const uint32_t*)(p0 + 8);
                af[mi][3] = *(const uint32_t*)(p0 + 8 * PITCH + 8);
            }
#pragma unroll
            for (int ni = 0; ni < 4; ni++) {
                const __nv_bfloat16* p0 =
                    &Bs[(wn + ni * 8 + (lane >> 2)) * PITCH + kb + (lane & 3) * 2];
                bf[ni][0] = *(const uint32_t*)p0;
                bf[ni][1] = *(const uint32_t*)(p0 + 8);
            }
#pragma unroll
            for (int mi = 0; mi < 4; mi++)
#pragma unroll
                for (int ni = 0; ni < 4; ni++)
                    mma_bf16(acc[mi][ni], af[mi][0], af[mi][1], af[mi][2], af[mi][3],
                             bf[ni][0], bf[ni][1]);
        }
        __syncthreads();
    }

    const float qs = g_scalars[0];
    auto store_row = [&](int row, int fcol, float v0, float v1) {
        if (row >= MP) return;
        int bl = fcol >= NN;
        int col = fcol - (bl ? NN : 0);
        int bb = bz2 + bl;
        float bias = (row < 32) ? bq[row] : (row < 64) ? bk[row - 32] : bv[row - 64];
        v0 += bias; v1 += bias;
        if (row < 32) {
            __nv_bfloat16* q = g_qh + (size_t)bb * NN * CQ;
            q[(size_t)col * CQ + row] = __float2bfloat16(v0 * qs);
            q[(size_t)(col + 1) * CQ + row] = __float2bfloat16(v1 * qs);
        } else if (row < 64) {
            __nv_bfloat16* k = g_kh + (size_t)bb * NN * CQ;
            k[(size_t)col * CQ + row - 32] = __float2bfloat16(v0);
            k[(size_t)(col + 1) * CQ + row - 32] = __float2bfloat16(v1);
        } else {
            __nv_bfloat16* v = g_vh + (size_t)bb * CC * NN;
            *(__nv_bfloat162*)(v + (size_t)(row - 64) * NN + col) =
                __floats2bfloat162_rn(v0, v1);
        }
    };

#pragma unroll
    for (int mi = 0; mi < 4; mi++)
#pragma unroll
        for (int ni = 0; ni < 4; ni++) {
            int row = m0 + wm + mi * 16 + (lane >> 2);
            int fcol = n0 + wn + ni * 8 + (lane & 3) * 2;
            store_row(row, fcol, acc[mi][ni][0], acc[mi][ni][1]);
            store_row(row + 8, fcol, acc[mi][ni][2], acc[mi][ni][3]);
        }
}

// ---------------- fused flash attention (R12 skeleton + split barrier + P reuse) ----
// 8 warps = 2m x 4j (S) / 2m x 4c (PV). Mid-stage barrier is a NAMED barrier
// over the 128 threads sharing mw (P rows are mw-local), so the two row-halves
// never wait on each other's S phase. Each warp keeps its own 16x16 P fragment
// in registers and skips that ldsm in PV.
__global__ __launch_bounds__(256, 2) void flash_kernel(float* __restrict__ out,
                                                       const float* __restrict__ xr,
                                                       const float* __restrict__ gamma,
                                                       float inv_bound) {
    extern __shared__ char dsm[];
    __nv_bfloat16* Ks = (__nv_bfloat16*)dsm;                   // 2*KSTG
    __nv_bfloat16* Vs = (__nv_bfloat16*)(dsm + 2 * KSTG * 2);  // 2*VSTG
    __nv_bfloat16* Ps = (__nv_bfloat16*)(dsm + PS_OFF);        // [32][PP]
    float* l_s = (float*)(dsm + LS_OFF);                       // [4][32]
    float* Obuf = (float*)(dsm);                               // epilogue reuse

    const int tid = threadIdx.x;
    const int lane = tid & 31;
    const int wid = tid >> 5;
    const int mw = wid >> 2;     // 0..1 : row half
    const int jw = wid & 3;      // S: key slice; PV: channel slice
    const int b = blockIdx.y;
    const int n0 = blockIdx.x * BM;

    const __nv_bfloat16* qg = g_qh + ((size_t)b * NN + n0 + mw * 16) * CQ;
    const __nv_bfloat16* kg = g_kh + (size_t)b * NN * CQ;
    const __nv_bfloat16* vg = g_vh + (size_t)b * CC * NN;

    uint32_t aq[2][4];
    {
        int r = lane >> 2;
#pragma unroll
        for (int kc = 0; kc < 2; kc++) {
            int kk = kc * 16 + (lane & 3) * 2;
            aq[kc][0] = *(const uint32_t*)(qg + (size_t)r * CQ + kk);
            aq[kc][1] = *(const uint32_t*)(qg + (size_t)(r + 8) * CQ + kk);
            aq[kc][2] = *(const uint32_t*)(qg + (size_t)r * CQ + kk + 8);
            aq[kc][3] = *(const uint32_t*)(qg + (size_t)(r + 8) * CQ + kk + 8);
        }
    }

    float o[8][4];
#pragma unroll
    for (int i = 0; i < 8; i++) { o[i][0] = o[i][1] = o[i][2] = o[i][3] = 0.f; }
    float accA = 0.f, accB = 0.f;

    const int krow = tid >> 2, kch = tid & 3;
    const int vrow = tid >> 3, vch = tid & 7;
    auto load_stage = [&](int s, int buf) {
        int j0 = s * BJ;
        cp16((uint32_t)__cvta_generic_to_shared(Ks + buf * KSTG + krow * KP + kch * 8),
             kg + (size_t)(j0 + krow) * CQ + kch * 8);
#pragma unroll
        for (int p = 0; p < 8; p++) {
            int c = vrow + p * 32;
            cp16((uint32_t)__cvta_generic_to_shared(Vs + buf * VSTG + c * VP + vch * 8),
                 vg + (size_t)c * NN + j0 + vch * 8);
        }
    };

    const uint32_t ksb = (uint32_t)__cvta_generic_to_shared(Ks) +
                         ((jw * 16 + (lane & 7)) * KP + (lane >> 3) * 8) * 2;
    const uint32_t vsb = (uint32_t)__cvta_generic_to_shared(Vs) +
                         ((jw * 64 + (lane >> 4) * 8 + (lane & 7)) * VP +
                          ((lane >> 3) & 1) * 8) * 2;
    const uint32_t psb = (uint32_t)__cvta_generic_to_shared(Ps) +
                         ((mw * 16 + (lane & 15)) * PP + (lane >> 4) * 8) * 2;

    const int prow = mw * 16 + (lane >> 2);
    __nv_bfloat16* pst = Ps + prow * PP + jw * 16 + (lane & 3) * 2;
    const int barid = 1 + mw;   // named barriers 1,2; __syncthreads uses 0

    load_stage(0, 0);
    CP_COMMIT();

    for (int s = 0; s < NST; s++) {
        if (s + 1 < NST) {
            load_stage(s + 1, (s + 1) & 1);
            CP_COMMIT();
            CP_WAIT1();
        } else {
            CP_WAIT0();
        }
        __syncthreads();   // K/V tile ready; previous PV done reading Ps

        const int buf = s & 1;
        const uint32_t kb = ksb + buf * (KSTG * 2);
        const uint32_t vb = vsb + buf * (VSTG * 2);

        // ---- S phase: 16 rows x 16 keys; keep own fragment in regs ----
        uint32_t own[4];
#pragma unroll
        for (int nt = 0; nt < 2; nt++) {
            float sv[4];
            sv[0] = sv[1] = sv[2] = sv[3] = 0.f;
            uint32_t k0, k1, k2, k3;
            ldsm4(k0, k1, k2, k3, kb + nt * (8 * KP * 2));
            mma_bf16(sv, aq[0][0], aq[0][1], aq[0][2], aq[0][3], k0, k1);
            mma_bf16(sv, aq[1][0], aq[1][1], aq[1][2], aq[1][3], k2, k3);

            float p0 = __expf(fminf(sv[0], 60.f));
            float p1 = __expf(fminf(sv[1], 60.f));
            float p2 = __expf(fminf(sv[2], 60.f));
            float p3 = __expf(fminf(sv[3], 60.f));
            accA += p0 + p1;
            accB += p2 + p3;
            uint32_t u01 = pack_bf16(p0, p1);
            uint32_t u23 = pack_bf16(p2, p3);
            own[nt * 2 + 0] = u01;      // a0 (nt=0) / a2 (nt=1)
            own[nt * 2 + 1] = u23;      // a1 (nt=0) / a3 (nt=1)
            *(uint32_t*)(pst + nt * 8) = u01;
            *(uint32_t*)(pst + 8 * PP + nt * 8) = u23;
        }
        // producer->consumer sync only within this mw half (128 threads)
        asm volatile("bar.sync %0, 128;\n" ::"r"(barid) : "memory");

        // ---- PV phase: full 64 keys x this warp's 64 channels ----
        uint32_t ap[4][4];
#pragma unroll
        for (int kt = 0; kt < 4; kt++) {
            if (kt == jw) {
                ap[kt][0] = own[0]; ap[kt][1] = own[1];
                ap[kt][2] = own[2]; ap[kt][3] = own[3];
            } else {
                ldsm4(ap[kt][0], ap[kt][1], ap[kt][2], ap[kt][3], psb + kt * 32);
            }
        }
#pragma unroll
        for (int kt = 0; kt < 4; kt++) {
#pragma unroll
            for (int ctp = 0; ctp < 4; ctp++) {
                uint32_t v0, v1, v2, v3;
                ldsm4(v0, v1, v2, v3, vb + ctp * (16 * VP * 2) + kt * 32);
                mma_bf16(o[2 * ctp], ap[kt][0], ap[kt][1], ap[kt][2], ap[kt][3],
                         v0, v1);
                mma_bf16(o[2 * ctp + 1], ap[kt][0], ap[kt][1], ap[kt][2], ap[kt][3],
                         v2, v3);
            }
        }
    }

    // ---- merge denominators across the 4 j-slices ----
    accA += __shfl_xor_sync(0xffffffffu, accA, 1);
    accA += __shfl_xor_sync(0xffffffffu, accA, 2);
    accB += __shfl_xor_sync(0xffffffffu, accB, 1);
    accB += __shfl_xor_sync(0xffffffffu, accB, 2);
    const int rA = mw * 16 + (lane >> 2);
    const int rB = rA + 8;
    if ((lane & 3) == 0) {
        l_s[jw * 32 + rA] = accA;
        l_s[jw * 32 + rB] = accB;
    }
    __syncthreads();
    const float invA =
        1.0f / (l_s[rA] + l_s[32 + rA] + l_s[64 + rA] + l_s[96 + rA]);
    const float invB =
        1.0f / (l_s[rB] + l_s[32 + rB] + l_s[64 + rB] + l_s[96 + rB]);
    __syncthreads();   // all l_s reads done; K/V smem reusable as Obuf

#pragma unroll
    for (int ct = 0; ct < 8; ct++) {
        int c = jw * 64 + ct * 8 + 2 * (lane & 3);
        float* pA = Obuf + rA * OBP + c;
        float* pB = Obuf + rB * OBP + c;
        pA[0] = o[ct][0] * invA; pA[1] = o[ct][1] * invA;
        pB[0] = o[ct][2] * invB; pB[1] = o[ct][3] * invB;
    }
    __syncthreads();

    const float gscale = gamma[0] * inv_bound;
    const float* xb = xr + (size_t)b * CC * NN;
    float* ob = out + (size_t)b * CC * NN;
    const int i = lane;
    const int crow = tid >> 5;
    for (int cb = 0; cb < CC; cb += 8) {
        int c = cb + crow;
        float val = Obuf[i * OBP + c];
        size_t off = (size_t)c * NN + n0 + i;
        ob[off] = fmaf(gscale, val, xb[off]);
    }
}

// ---------------- launch ----------------
extern "C" void kernel_launch(void* const* d_in, const int* in_sizes, int n_in,
                              void* d_out, int out_size) {
    const float* x = (const float*)d_in[0];
    const float* Wq = (const float*)d_in[1];
    const float* bq = (const float*)d_in[2];
    const float* Wk = (const float*)d_in[3];
    const float* bk = (const float*)d_in[4];
    const float* Wv = (const float*)d_in[5];
    const float* bv = (const float*)d_in[6];
    const float* gamma = (const float*)d_in[7];
    float* out = (float*)d_out;

    cudaFuncSetAttribute(flash_kernel, cudaFuncAttributeMaxDynamicSharedMemorySize,
                         SMEM_BYTES);

    norm_kernel<<<1, 256>>>(Wq, Wk, Wv);
    prep_w<<<MP, CC>>>(Wq, Wk, Wv);
    xpose<<<dim3(NN / 32, CC / 32, BB), 256>>>(x);
    proj_mma<<<dim3(49, 3, 2), 256>>>(bq, bk, bv);

    double bound = exp(sqrt(3.0)) * sqrt((double)NN / (double)CC) + 2.0 * sqrt(6.0);
    float inv_bound = (float)(1.0 / bound);
    flash_kernel<<<dim3(NN / BM, BB), 256, SMEM_BYTES>>>(out, x, gamma, inv_bound);
}